// round 1
// baseline (speedup 1.0000x reference)
#include <cuda_runtime.h>

#define TRACES 4096
#define LSEQ   64
#define ISZ    64
#define HSZ    128

// Per-trace embedding scratch (2 MB) — static device global (no allocation).
__device__ float g_trace_emb[TRACES * HSZ];

// Shared memory layout (float offsets)
#define OFF_X   0                       // [64][64]   gathered embeddings
#define OFF_H1  4096                    // [64][128]  layer-1 hidden
#define OFF_H2  12288                   // [64][128]  layer-2 hidden
#define OFF_W   20480                   // [128][132] staged weight tile
#define OFF_E   (20480 + 128*132)       // [64]       energies / softmax weights
#define SMEM_FLOATS (OFF_E + 64)
#define WSTRIDE 132                     // 132 % 32 == 4 -> conflict-free LDS.128

// Cooperatively stage a [128 x K] weight block (row-major in gmem) into sW
// with padded stride. 512 threads, coalesced float4 loads.
template <int K>
__device__ __forceinline__ void stage_w(const float* __restrict__ g, float* sW, int t) {
    constexpr int NF4 = 128 * K / 4;
#pragma unroll
    for (int q = 0; q < NF4 / 512; q++) {
        int fid = q * 512 + t;
        int r = fid / (K / 4);
        int c = (fid % (K / 4)) * 4;
        *(float4*)(sW + r * WSTRIDE + c) = *(const float4*)(g + r * K + c);
    }
}

// Accumulate a 4(gate-rows) x 4(tokens) micro-tile: acc[m][tt] += sum_k
// sW[j+32m][k] * sIn[t0+tt][k].  Lanes hold consecutive j -> broadcast X
// reads, conflict-free W reads.
template <int K>
__device__ __forceinline__ void mm_accum(const float* __restrict__ sIn,
                                         const float* __restrict__ sW,
                                         int j, int t0, float acc[4][4]) {
#pragma unroll 2
    for (int kk = 0; kk < K; kk += 8) {
        float4 w0[4], w1[4];
#pragma unroll
        for (int m = 0; m < 4; m++) {
            const float* wr = sW + (j + 32 * m) * WSTRIDE + kk;
            w0[m] = *(const float4*)wr;
            w1[m] = *(const float4*)(wr + 4);
        }
#pragma unroll
        for (int tt = 0; tt < 4; tt++) {
            const float* xr = sIn + (t0 + tt) * K + kk;
            float4 x0 = *(const float4*)xr;
            float4 x1 = *(const float4*)(xr + 4);
#pragma unroll
            for (int m = 0; m < 4; m++) {
                float a = acc[m][tt];
                a = fmaf(w0[m].x, x0.x, a);
                a = fmaf(w0[m].y, x0.y, a);
                a = fmaf(w0[m].z, x0.z, a);
                a = fmaf(w0[m].w, x0.w, a);
                a = fmaf(w1[m].x, x1.x, a);
                a = fmaf(w1[m].y, x1.y, a);
                a = fmaf(w1[m].z, x1.z, a);
                a = fmaf(w1[m].w, x1.w, a);
                acc[m][tt] = a;
            }
        }
    }
}

__device__ __forceinline__ float sigm(float x) {
    return 1.0f / (1.0f + __expf(-x));
}

// One LSTM layer from zero state: h = sigmoid(o)*tanh(sigmoid(i)*tanh(c_hat)).
// Gate rows in W: i=[0,128), f=[128,256) (dead), c_hat=[256,384), o=[384,512).
template <int K>
__device__ __forceinline__ void lstm_layer(const float* __restrict__ sIn,
                                           float* __restrict__ sOut,
                                           float* __restrict__ sW,
                                           const float* __restrict__ W,
                                           const float* __restrict__ bi,
                                           const float* __restrict__ bh,
                                           int t) {
    const int j  = t & 31;
    const int t0 = (t >> 5) * 4;
    float acc[3][4][4];
#pragma unroll
    for (int s = 0; s < 3; s++)
#pragma unroll
        for (int m = 0; m < 4; m++)
#pragma unroll
            for (int tt = 0; tt < 4; tt++) acc[s][m][tt] = 0.f;

#pragma unroll
    for (int s = 0; s < 3; s++) {
        const int base = (s == 0) ? 0 : (s == 1) ? 2 * HSZ : 3 * HSZ;
        __syncthreads();                       // protect sW from prior readers
        stage_w<K>(W + base * K, sW, t);
        __syncthreads();
        mm_accum<K>(sIn, sW, j, t0, acc[s]);
    }

#pragma unroll
    for (int m = 0; m < 4; m++) {
        int g = j + 32 * m;
        float bI = bi[g] + bh[g];
        float bC = bi[2 * HSZ + g] + bh[2 * HSZ + g];
        float bO = bi[3 * HSZ + g] + bh[3 * HSZ + g];
#pragma unroll
        for (int tt = 0; tt < 4; tt++) {
            float ig = sigm(acc[0][m][tt] + bI);
            float c  = ig * tanhf(acc[1][m][tt] + bC);
            float og = sigm(acc[2][m][tt] + bO);
            sOut[(t0 + tt) * HSZ + g] = og * tanhf(c);
        }
    }
}

__global__ __launch_bounds__(512, 1) void fused_trace_kernel(
    const float* __restrict__ emb,
    const float* __restrict__ W1,
    const float* __restrict__ bi1, const float* __restrict__ bh1,
    const float* __restrict__ W2,
    const float* __restrict__ bi2, const float* __restrict__ bh2,
    const float* __restrict__ Wp1, const float* __restrict__ bp1,
    const float* __restrict__ Wp2, const float* __restrict__ bp2,
    const int* __restrict__ traces, const int* __restrict__ lengths)
{
    extern __shared__ float sm[];
    const int t = threadIdx.x;
    const int trace = blockIdx.x;

    // ---- Gather token embeddings: X[64][64] ----
    {
        int l = t >> 3;          // token
        int seg = t & 7;         // 8 floats each
        int id = traces[trace * LSEQ + l];
        const float4* src = (const float4*)(emb + id * ISZ + seg * 8);
        float4* dst = (float4*)(sm + OFF_X + l * ISZ + seg * 8);
        dst[0] = src[0];
        dst[1] = src[1];
    }
    // (visibility covered by first __syncthreads inside lstm_layer)

    // ---- LSTM layer 1 (K=64) and layer 2 (K=128) ----
    lstm_layer<ISZ>(sm + OFF_X, sm + OFF_H1, sm + OFF_W, W1, bi1, bh1, t);
    lstm_layer<HSZ>(sm + OFF_H1, sm + OFF_H2, sm + OFF_W, W2, bi2, bh2, t);

    // ---- Attention MLP: energy[l] = relu(h2 @ Wp1^T + bp1) @ Wp2^T + bp2 ----
    __syncthreads();
    {   // stage Wp1 [64 x 128]
#pragma unroll
        for (int q = 0; q < 4; q++) {
            int fid = q * 512 + t;
            int r = fid >> 5;
            int c = (fid & 31) * 4;
            *(float4*)(sm + OFF_W + r * WSTRIDE + c) = *(const float4*)(Wp1 + r * HSZ + c);
        }
    }
    __syncthreads();
    {
        const int token = t >> 3;   // 64 tokens
        const int pi = t & 7;       // 8 p-lanes per token, each owns 8 p's
        float accp[8];
#pragma unroll
        for (int m = 0; m < 8; m++) accp[m] = 0.f;
#pragma unroll 2
        for (int kk = 0; kk < HSZ; kk += 8) {
            const float* hr = sm + OFF_H2 + token * HSZ + kk;
            float4 h0 = *(const float4*)hr;
            float4 h1 = *(const float4*)(hr + 4);
#pragma unroll
            for (int m = 0; m < 8; m++) {
                const float* wr = sm + OFF_W + (pi + 8 * m) * WSTRIDE + kk;
                float4 w0 = *(const float4*)wr;
                float4 w1 = *(const float4*)(wr + 4);
                float a = accp[m];
                a = fmaf(w0.x, h0.x, a); a = fmaf(w0.y, h0.y, a);
                a = fmaf(w0.z, h0.z, a); a = fmaf(w0.w, h0.w, a);
                a = fmaf(w1.x, h1.x, a); a = fmaf(w1.y, h1.y, a);
                a = fmaf(w1.z, h1.z, a); a = fmaf(w1.w, h1.w, a);
                accp[m] = a;
            }
        }
        float partial = 0.f;
#pragma unroll
        for (int m = 0; m < 8; m++) {
            float pv = accp[m] + bp1[pi + 8 * m];
            pv = fmaxf(pv, 0.f);
            partial = fmaf(pv, Wp2[pi + 8 * m], partial);
        }
        partial += __shfl_down_sync(0xffffffffu, partial, 4, 8);
        partial += __shfl_down_sync(0xffffffffu, partial, 2, 8);
        partial += __shfl_down_sync(0xffffffffu, partial, 1, 8);
        if (pi == 0) sm[OFF_E + token] = partial + bp2[0];
    }
    __syncthreads();

    // ---- Masked softmax over 64 positions (warp 0) ----
    if (t < 32) {
        int len = lengths[trace];
        float v0 = (t      < len) ? sm[OFF_E + t]      : -1e30f;
        float v1 = (t + 32 < len) ? sm[OFF_E + t + 32] : -1e30f;
        float mx = fmaxf(v0, v1);
#pragma unroll
        for (int off = 16; off > 0; off >>= 1)
            mx = fmaxf(mx, __shfl_xor_sync(0xffffffffu, mx, off));
        float e0 = __expf(v0 - mx);
        float e1 = __expf(v1 - mx);
        float ss = e0 + e1;
#pragma unroll
        for (int off = 16; off > 0; off >>= 1)
            ss += __shfl_xor_sync(0xffffffffu, ss, off);
        float inv = __fdividef(1.0f, ss);
        sm[OFF_E + t]      = e0 * inv;
        sm[OFF_E + t + 32] = e1 * inv;
    }
    __syncthreads();

    // ---- Weighted sum over positions -> per-trace embedding ----
    if (t < HSZ) {
        float acc = 0.f;
#pragma unroll 4
        for (int l = 0; l < LSEQ; l++)
            acc = fmaf(sm[OFF_E + l], sm[OFF_H2 + l * HSZ + t], acc);
        g_trace_emb[trace * HSZ + t] = acc;
    }
}

// Deterministic reduction over traces + final 128x128 matvec.
__global__ __launch_bounds__(128) void reduce_out_kernel(
    const float* __restrict__ Wout, const float* __restrict__ bout,
    float* __restrict__ out)
{
    __shared__ float sfinal[HSZ];
    const int t = threadIdx.x;
    float s = 0.f;
#pragma unroll 8
    for (int tr = 0; tr < TRACES; tr++)
        s += g_trace_emb[tr * HSZ + t];
    sfinal[t] = s;
    __syncthreads();
    float o = bout[t];
#pragma unroll 4
    for (int h = 0; h < HSZ; h++)
        o = fmaf(Wout[t * HSZ + h], sfinal[h], o);
    out[t] = o;
}

extern "C" void kernel_launch(void* const* d_in, const int* in_sizes, int n_in,
                              void* d_out, int out_size) {
    const float* emb    = (const float*)d_in[0];
    const float* W1     = (const float*)d_in[1];
    // d_in[2] = W_hh1 (unused: h0 = 0)
    const float* bi1    = (const float*)d_in[3];
    const float* bh1    = (const float*)d_in[4];
    const float* W2     = (const float*)d_in[5];
    // d_in[6] = W_hh2 (unused)
    const float* bi2    = (const float*)d_in[7];
    const float* bh2    = (const float*)d_in[8];
    const float* Wp1    = (const float*)d_in[9];
    const float* bp1    = (const float*)d_in[10];
    const float* Wp2    = (const float*)d_in[11];
    const float* bp2    = (const float*)d_in[12];
    const float* Wout   = (const float*)d_in[13];
    const float* bout   = (const float*)d_in[14];
    const int*   traces = (const int*)d_in[15];
    const int*   lens   = (const int*)d_in[16];

    cudaFuncSetAttribute(fused_trace_kernel,
                         cudaFuncAttributeMaxDynamicSharedMemorySize,
                         SMEM_FLOATS * sizeof(float));

    fused_trace_kernel<<<TRACES, 512, SMEM_FLOATS * sizeof(float)>>>(
        emb, W1, bi1, bh1, W2, bi2, bh2, Wp1, bp1, Wp2, bp2, traces, lens);

    reduce_out_kernel<<<1, 128>>>(Wout, bout, (float*)d_out);
}

// round 2
// speedup vs baseline: 1.2796x; 1.2796x over previous
#include <cuda_runtime.h>

#define TRACES 4096
#define LSEQ   64
#define ISZ    64
#define HSZ    128
#define RBLK   256            // reduction stage-1 blocks (16 traces each)

typedef unsigned long long ull;

// Scratch (static device globals — no allocation).
__device__ float g_trace_emb[TRACES * HSZ];
__device__ float g_partial[RBLK * HSZ];

// Shared memory layout (float offsets)
#define OFF_X   0                       // [64][64]   gathered embeddings
#define OFF_H1  4096                    // [64][128]  layer-1 hidden
#define OFF_H2  12288                   // [64][128]  layer-2 hidden
#define OFF_W   20480                   // [128][132] staged weight tile
#define OFF_E   (20480 + 128*132)       // [64]       energies / softmax weights
#define SMEM_FLOATS (OFF_E + 64)
#define WSTRIDE 132                     // conflict-free LDS.128 (4-bank skew)

// ---- packed f32x2 FMA (FFMA2) ----
__device__ __forceinline__ void fma2(ull& d, ull a, ull b) {
    asm("fma.rn.f32x2 %0, %1, %2, %0;" : "+l"(d) : "l"(a), "l"(b));
}
__device__ __forceinline__ float sum2(ull v) {
    union { ull u; float2 f; } c; c.u = v;
    return c.f.x + c.f.y;
}
__device__ __forceinline__ float tanh_ap(float x) {
    float y; asm("tanh.approx.f32 %0, %1;" : "=f"(y) : "f"(x)); return y;
}
__device__ __forceinline__ float sigm(float x) {
    return fmaf(0.5f, tanh_ap(0.5f * x), 0.5f);
}

// Cooperatively stage a [128 x K] weight block into sW with padded stride.
template <int K>
__device__ __forceinline__ void stage_w(const float* __restrict__ g, float* sW, int t) {
    constexpr int NF4 = 128 * K / 4;
#pragma unroll
    for (int q = 0; q < NF4 / 512; q++) {
        int fid = q * 512 + t;
        int r = fid / (K / 4);
        int c = (fid % (K / 4)) * 4;
        *(float4*)(sW + r * WSTRIDE + c) = *(const float4*)(g + r * K + c);
    }
}

// 4(gate-rows) x 4(tokens) micro-tile with packed f32x2 accumulators.
// acc[m][tt] holds (even-k partial, odd-k partial).
template <int K>
__device__ __forceinline__ void mm_accum2(const float* __restrict__ sIn,
                                          const float* __restrict__ sW,
                                          int j, int t0, ull acc[4][4]) {
#pragma unroll 4
    for (int kk = 0; kk < K; kk += 8) {
        ulonglong2 wA[4], wB[4];
#pragma unroll
        for (int m = 0; m < 4; m++) {
            const float* wr = sW + (j + 32 * m) * WSTRIDE + kk;
            wA[m] = *(const ulonglong2*)wr;
            wB[m] = *(const ulonglong2*)(wr + 4);
        }
#pragma unroll
        for (int tt = 0; tt < 4; tt++) {
            const float* xr = sIn + (t0 + tt) * K + kk;
            ulonglong2 xA = *(const ulonglong2*)xr;
            ulonglong2 xB = *(const ulonglong2*)(xr + 4);
#pragma unroll
            for (int m = 0; m < 4; m++) {
                fma2(acc[m][tt], wA[m].x, xA.x);
                fma2(acc[m][tt], wA[m].y, xA.y);
                fma2(acc[m][tt], wB[m].x, xB.x);
                fma2(acc[m][tt], wB[m].y, xB.y);
            }
        }
    }
}

// One LSTM layer from zero state. Gate rows: i=[0,128), f dead, c_hat=[256,384),
// o=[384,512). Activation folded per stage to cap register pressure.
template <int K>
__device__ __forceinline__ void lstm_layer(const float* __restrict__ sIn,
                                           float* __restrict__ sOut,
                                           float* __restrict__ sW,
                                           const float* __restrict__ W,
                                           const float* __restrict__ bi,
                                           const float* __restrict__ bh,
                                           int t) {
    const int j  = t & 31;
    const int t0 = (t >> 5) * 4;
    float carry[4][4];   // stage0: sigmoid(i); stage1: c; stage2 writes h

#pragma unroll
    for (int s = 0; s < 3; s++) {
        const int base = (s == 0) ? 0 : (s == 1) ? 2 * HSZ : 3 * HSZ;
        __syncthreads();                       // protect sW from prior readers
        stage_w<K>(W + base * K, sW, t);
        __syncthreads();

        ull acc[4][4];
#pragma unroll
        for (int m = 0; m < 4; m++)
#pragma unroll
            for (int tt = 0; tt < 4; tt++) acc[m][tt] = 0ULL;

        mm_accum2<K>(sIn, sW, j, t0, acc);

#pragma unroll
        for (int m = 0; m < 4; m++) {
            int g = base + j + 32 * m;
            float b = bi[g] + bh[g];
#pragma unroll
            for (int tt = 0; tt < 4; tt++) {
                float v = sum2(acc[m][tt]) + b;
                if (s == 0) {
                    carry[m][tt] = sigm(v);
                } else if (s == 1) {
                    carry[m][tt] = carry[m][tt] * tanh_ap(v);
                } else {
                    sOut[(t0 + tt) * HSZ + (j + 32 * m)] =
                        sigm(v) * tanh_ap(carry[m][tt]);
                }
            }
        }
    }
}

__global__ __launch_bounds__(512, 1) void fused_trace_kernel(
    const float* __restrict__ emb,
    const float* __restrict__ W1,
    const float* __restrict__ bi1, const float* __restrict__ bh1,
    const float* __restrict__ W2,
    const float* __restrict__ bi2, const float* __restrict__ bh2,
    const float* __restrict__ Wp1, const float* __restrict__ bp1,
    const float* __restrict__ Wp2, const float* __restrict__ bp2,
    const int* __restrict__ traces, const int* __restrict__ lengths)
{
    extern __shared__ float sm[];
    const int t = threadIdx.x;
    const int trace = blockIdx.x;

    // ---- Gather token embeddings: X[64][64] ----
    {
        int l = t >> 3;
        int seg = t & 7;
        int id = traces[trace * LSEQ + l];
        const float4* src = (const float4*)(emb + id * ISZ + seg * 8);
        float4* dst = (float4*)(sm + OFF_X + l * ISZ + seg * 8);
        dst[0] = src[0];
        dst[1] = src[1];
    }
    // first __syncthreads inside lstm_layer covers visibility

    lstm_layer<ISZ>(sm + OFF_X, sm + OFF_H1, sm + OFF_W, W1, bi1, bh1, t);
    lstm_layer<HSZ>(sm + OFF_H1, sm + OFF_H2, sm + OFF_W, W2, bi2, bh2, t);

    // ---- Attention MLP: energy[l] = relu(h2 @ Wp1^T + bp1) @ Wp2^T + bp2 ----
    __syncthreads();
    {   // stage Wp1 [64 x 128]
#pragma unroll
        for (int q = 0; q < 4; q++) {
            int fid = q * 512 + t;
            int r = fid >> 5;
            int c = (fid & 31) * 4;
            *(float4*)(sm + OFF_W + r * WSTRIDE + c) = *(const float4*)(Wp1 + r * HSZ + c);
        }
    }
    __syncthreads();
    {
        const int token = t >> 3;
        const int pi = t & 7;
        ull accp[8];
#pragma unroll
        for (int m = 0; m < 8; m++) accp[m] = 0ULL;
#pragma unroll 4
        for (int kk = 0; kk < HSZ; kk += 8) {
            const float* hr = sm + OFF_H2 + token * HSZ + kk;
            ulonglong2 hA = *(const ulonglong2*)hr;
            ulonglong2 hB = *(const ulonglong2*)(hr + 4);
#pragma unroll
            for (int m = 0; m < 8; m++) {
                const float* wr = sm + OFF_W + (pi + 8 * m) * WSTRIDE + kk;
                ulonglong2 wA = *(const ulonglong2*)wr;
                ulonglong2 wB = *(const ulonglong2*)(wr + 4);
                fma2(accp[m], wA.x, hA.x);
                fma2(accp[m], wA.y, hA.y);
                fma2(accp[m], wB.x, hB.x);
                fma2(accp[m], wB.y, hB.y);
            }
        }
        float partial = 0.f;
#pragma unroll
        for (int m = 0; m < 8; m++) {
            float pv = sum2(accp[m]) + bp1[pi + 8 * m];
            pv = fmaxf(pv, 0.f);
            partial = fmaf(pv, Wp2[pi + 8 * m], partial);
        }
        partial += __shfl_down_sync(0xffffffffu, partial, 4, 8);
        partial += __shfl_down_sync(0xffffffffu, partial, 2, 8);
        partial += __shfl_down_sync(0xffffffffu, partial, 1, 8);
        if (pi == 0) sm[OFF_E + token] = partial + bp2[0];
    }
    __syncthreads();

    // ---- Masked softmax over 64 positions (warp 0) ----
    if (t < 32) {
        int len = lengths[trace];
        float v0 = (t      < len) ? sm[OFF_E + t]      : -1e30f;
        float v1 = (t + 32 < len) ? sm[OFF_E + t + 32] : -1e30f;
        float mx = fmaxf(v0, v1);
#pragma unroll
        for (int off = 16; off > 0; off >>= 1)
            mx = fmaxf(mx, __shfl_xor_sync(0xffffffffu, mx, off));
        float e0 = __expf(v0 - mx);
        float e1 = __expf(v1 - mx);
        float ss = e0 + e1;
#pragma unroll
        for (int off = 16; off > 0; off >>= 1)
            ss += __shfl_xor_sync(0xffffffffu, ss, off);
        float inv = __fdividef(1.0f, ss);
        sm[OFF_E + t]      = e0 * inv;
        sm[OFF_E + t + 32] = e1 * inv;
    }
    __syncthreads();

    // ---- Weighted sum over positions -> per-trace embedding ----
    if (t < HSZ) {
        float acc = 0.f;
#pragma unroll 4
        for (int l = 0; l < LSEQ; l++)
            acc = fmaf(sm[OFF_E + l], sm[OFF_H2 + l * HSZ + t], acc);
        g_trace_emb[trace * HSZ + t] = acc;
    }
}

// Stage-1 reduction: 256 blocks, each sums 16 traces (deterministic partition).
__global__ __launch_bounds__(128) void reduce_part_kernel() {
    const int b = blockIdx.x;
    const int t = threadIdx.x;
    float s = 0.f;
    const int tr0 = b * (TRACES / RBLK);
#pragma unroll
    for (int i = 0; i < TRACES / RBLK; i++)
        s += g_trace_emb[(tr0 + i) * HSZ + t];
    g_partial[b * HSZ + t] = s;
}

// Stage-2: sum partials + final 128x128 matvec.
__global__ __launch_bounds__(128) void reduce_out_kernel(
    const float* __restrict__ Wout, const float* __restrict__ bout,
    float* __restrict__ out)
{
    __shared__ float sfinal[HSZ];
    const int t = threadIdx.x;
    float s = 0.f;
#pragma unroll 8
    for (int p = 0; p < RBLK; p++)
        s += g_partial[p * HSZ + t];
    sfinal[t] = s;
    __syncthreads();
    float o = bout[t];
#pragma unroll 4
    for (int h = 0; h < HSZ; h++)
        o = fmaf(Wout[t * HSZ + h], sfinal[h], o);
    out[t] = o;
}

extern "C" void kernel_launch(void* const* d_in, const int* in_sizes, int n_in,
                              void* d_out, int out_size) {
    const float* emb    = (const float*)d_in[0];
    const float* W1     = (const float*)d_in[1];
    const float* bi1    = (const float*)d_in[3];
    const float* bh1    = (const float*)d_in[4];
    const float* W2     = (const float*)d_in[5];
    const float* bi2    = (const float*)d_in[7];
    const float* bh2    = (const float*)d_in[8];
    const float* Wp1    = (const float*)d_in[9];
    const float* bp1    = (const float*)d_in[10];
    const float* Wp2    = (const float*)d_in[11];
    const float* bp2    = (const float*)d_in[12];
    const float* Wout   = (const float*)d_in[13];
    const float* bout   = (const float*)d_in[14];
    const int*   traces = (const int*)d_in[15];
    const int*   lens   = (const int*)d_in[16];

    cudaFuncSetAttribute(fused_trace_kernel,
                         cudaFuncAttributeMaxDynamicSharedMemorySize,
                         SMEM_FLOATS * sizeof(float));

    fused_trace_kernel<<<TRACES, 512, SMEM_FLOATS * sizeof(float)>>>(
        emb, W1, bi1, bh1, W2, bi2, bh2, Wp1, bp1, Wp2, bp2, traces, lens);

    reduce_part_kernel<<<RBLK, 128>>>();
    reduce_out_kernel<<<1, 128>>>(Wout, bout, (float*)d_out);
}